// round 6
// baseline (speedup 1.0000x reference)
#include <cuda_runtime.h>
#include <cuda_bf16.h>
#include <math.h>

// ---------------- problem constants ----------------
#define NMAX 100000
#define EMAX 3200000
#define DHID 128
#define DOUT 64

// ---------------- static scratch (allocation-free) ----------------
__device__ __nv_bfloat16 g_hb1[NMAX * DHID];   // layer1 GEMM out (bf16 for gather)
__device__ float g_agg1 [NMAX * DHID];         // layer1 aggregated (relu+bias fused)
__device__ __nv_bfloat16 g_hb2[NMAX * DOUT];   // layer2 GEMM out (bf16)
__device__ float g_agg2 [NMAX * DOUT];         // layer2 aggregated
__device__ float g_as   [NMAX];
__device__ float g_ad   [NMAX];
__device__ int   g_deg  [NMAX];                // in-degree incl. self-loop (after alloc)
__device__ int   g_off  [NMAX];
__device__ int   g_cur  [NMAX];
__device__ int   g_csrs [EMAX + NMAX];
__device__ int   g_counter;

__device__ __forceinline__ float leaky(float e) { return e > 0.f ? e : 0.2f * e; }

// ---------------- CSR build ----------------
__global__ void k_hist(const int* __restrict__ dstp, int E) {
    int i = blockIdx.x * blockDim.x + threadIdx.x;
    if (i < E) atomicAdd(&g_deg[dstp[i]], 1);
}

// Warp-aggregated offset allocation; self-loop placed first in each segment.
__global__ void k_alloc(int N) {
    int i    = blockIdx.x * blockDim.x + threadIdx.x;
    int lane = threadIdx.x & 31;
    int v    = (i < N) ? (g_deg[i] + 1) : 0;   // +1 self-loop
    int incl = v;
#pragma unroll
    for (int o = 1; o < 32; o <<= 1) {
        int t = __shfl_up_sync(0xffffffffu, incl, o);
        if (lane >= o) incl += t;
    }
    int total = __shfl_sync(0xffffffffu, incl, 31);
    int base  = 0;
    if (lane == 0) base = atomicAdd(&g_counter, total);
    base = __shfl_sync(0xffffffffu, base, 0);
    if (i < N) {
        int my = base + incl - v;
        g_deg[i]   = v;
        g_off[i]   = my;
        g_csrs[my] = i;        // self-loop first
        g_cur[i]   = my + 1;
    }
}

__global__ void k_scatter(const int* __restrict__ srcp, const int* __restrict__ dstp, int E) {
    int i = blockIdx.x * blockDim.x + threadIdx.x;
    if (i < E) {
        int d   = dstp[i];
        int pos = atomicAdd(&g_cur[d], 1);
        g_csrs[pos] = srcp[i];
    }
}

// ---------------- GEMM (f32x2 packed FMA) + fused dots + bf16 store ----------------
template<int FOUT>
__global__ void k_gemm2(const float* __restrict__ X, const float* __restrict__ W,
                        __nv_bfloat16* __restrict__ HB,
                        const float* __restrict__ avs, const float* __restrict__ avd,
                        int N) {
    constexpr int K  = 128;
    constexpr int BR = 64;
    constexpr int CG = FOUT / 8;   // 16 or 8
    constexpr int NT = CG * 16;    // 256 or 128 threads
    extern __shared__ float smem[];
    float* sW = smem;              // K * FOUT
    float* sX = smem + K * FOUT;   // BR * K

    int tid  = threadIdx.x;
    int row0 = blockIdx.x * BR;

    for (int i = tid; i < K * FOUT / 4; i += NT)
        ((float4*)sW)[i] = ((const float4*)W)[i];
    {
        int rows = N - row0; if (rows > BR) rows = BR;
        const float4* X4 = (const float4*)(X + (size_t)row0 * K);
        for (int i = tid; i < rows * (K / 4); i += NT) ((float4*)sX)[i] = X4[i];
    }
    __syncthreads();

    int tx = tid % CG;
    int ty = tid / CG;
    const unsigned long long* sW2 = (const unsigned long long*)sW;

    unsigned long long acc[4][4];
#pragma unroll
    for (int i = 0; i < 4; i++)
#pragma unroll
        for (int j = 0; j < 4; j++) acc[i][j] = 0ull;

#pragma unroll 4
    for (int k = 0; k < K; k++) {
        unsigned long long b0 = sW2[k * (FOUT / 2) + tx * 2];
        unsigned long long b1 = sW2[k * (FOUT / 2) + tx * 2 + 1];
        unsigned long long b2 = sW2[k * (FOUT / 2) + FOUT / 4 + tx * 2];
        unsigned long long b3 = sW2[k * (FOUT / 2) + FOUT / 4 + tx * 2 + 1];
#pragma unroll
        for (int i = 0; i < 4; i++) {
            unsigned xu = __float_as_uint(sX[(ty * 4 + i) * K + k]);
            unsigned long long a2;
            asm("mov.b64 %0, {%1, %1};" : "=l"(a2) : "r"(xu));
            asm("fma.rn.f32x2 %0, %1, %2, %0;" : "+l"(acc[i][0]) : "l"(a2), "l"(b0));
            asm("fma.rn.f32x2 %0, %1, %2, %0;" : "+l"(acc[i][1]) : "l"(a2), "l"(b1));
            asm("fma.rn.f32x2 %0, %1, %2, %0;" : "+l"(acc[i][2]) : "l"(a2), "l"(b2));
            asm("fma.rn.f32x2 %0, %1, %2, %0;" : "+l"(acc[i][3]) : "l"(a2), "l"(b3));
        }
    }

    // ---- epilogue: unpack, bf16 store, fused attention dots ----
    int c0 = tx * 4, c1 = FOUT / 2 + tx * 4;
    float as0[4], as1[4], ad0[4], ad1[4];
#pragma unroll
    for (int j = 0; j < 4; j++) {
        as0[j] = __ldg(&avs[c0 + j]); as1[j] = __ldg(&avs[c1 + j]);
        ad0[j] = __ldg(&avd[c0 + j]); ad1[j] = __ldg(&avd[c1 + j]);
    }

#pragma unroll
    for (int i = 0; i < 4; i++) {
        int row = row0 + ty * 4 + i;
        float c[8];
#pragma unroll
        for (int j = 0; j < 4; j++) {
            unsigned lo, hi;
            asm("mov.b64 {%0, %1}, %2;" : "=r"(lo), "=r"(hi) : "l"(acc[i][j]));
            c[j * 2]     = __uint_as_float(lo);
            c[j * 2 + 1] = __uint_as_float(hi);
        }
        float s1 = c[0]*as0[0] + c[1]*as0[1] + c[2]*as0[2] + c[3]*as0[3]
                 + c[4]*as1[0] + c[5]*as1[1] + c[6]*as1[2] + c[7]*as1[3];
        float s2 = c[0]*ad0[0] + c[1]*ad0[1] + c[2]*ad0[2] + c[3]*ad0[3]
                 + c[4]*ad1[0] + c[5]*ad1[1] + c[6]*ad1[2] + c[7]*ad1[3];
#pragma unroll
        for (int o = CG / 2; o > 0; o >>= 1) {
            s1 += __shfl_xor_sync(0xffffffffu, s1, o);
            s2 += __shfl_xor_sync(0xffffffffu, s2, o);
        }
        if (row < N) {
            __nv_bfloat162 p0 = __float22bfloat162_rn(make_float2(c[0], c[1]));
            __nv_bfloat162 p1 = __float22bfloat162_rn(make_float2(c[2], c[3]));
            __nv_bfloat162 p2 = __float22bfloat162_rn(make_float2(c[4], c[5]));
            __nv_bfloat162 p3 = __float22bfloat162_rn(make_float2(c[6], c[7]));
            uint2 u, v;
            u.x = *(unsigned*)&p0; u.y = *(unsigned*)&p1;
            v.x = *(unsigned*)&p2; v.y = *(unsigned*)&p3;
            *(uint2*)(HB + (size_t)row * FOUT + c0) = u;
            *(uint2*)(HB + (size_t)row * FOUT + c1) = v;
            if (tx == 0) { g_as[row] = s1; g_ad[row] = s2; }
        }
    }
}

// ---------------- fused attention: softmax + gather-aggregate (warp per node) ----------------
// Loop 1: lanes parallel over edges -> segment max.
// Loop 2: lanes = feature cols, sequential over edges; exp recomputed inline
//         (identical in all lanes, so the denominator needs no reduction).
template<int F, bool BIAS_RELU>
__global__ void k_attn(const __nv_bfloat16* __restrict__ HB, float* __restrict__ AGG,
                       const float* __restrict__ bias, int N) {
    int w    = (blockIdx.x * blockDim.x + threadIdx.x) >> 5;
    int lane = threadIdx.x & 31;
    if (w >= N) return;
    int   start = g_off[w];
    int   n     = g_deg[w];
    float adv   = g_ad[w];

    // loop 1: segment max
    float m = -INFINITY;
    for (int j = lane; j < n; j += 32) {
        int s = g_csrs[start + j];
        m = fmaxf(m, leaky(g_as[s] + adv));
    }
#pragma unroll
    for (int o = 16; o > 0; o >>= 1) m = fmaxf(m, __shfl_xor_sync(0xffffffffu, m, o));

    // loop 2: gather + accumulate (ss replicated across lanes)
    float ss = 0.f;
    if (F == 128) {
        const uint2* H2 = (const uint2*)HB;
        float4 acc = make_float4(0.f, 0.f, 0.f, 0.f);
#pragma unroll 2
        for (int j = 0; j < n; j++) {
            int   s  = g_csrs[start + j];
            float ex = __expf(leaky(g_as[s] + adv) - m);
            ss += ex;
            uint2 v = H2[(size_t)s * 32 + lane];
            float2 f0 = __bfloat1622float2(*(__nv_bfloat162*)&v.x);
            float2 f1 = __bfloat1622float2(*(__nv_bfloat162*)&v.y);
            acc.x += ex * f0.x; acc.y += ex * f0.y;
            acc.z += ex * f1.x; acc.w += ex * f1.y;
        }
        float inv = 1.f / (ss + 1e-16f);
        if (BIAS_RELU) {
            float4 bv = ((const float4*)bias)[lane];
            acc.x = fmaxf(acc.x * inv + bv.x, 0.f);
            acc.y = fmaxf(acc.y * inv + bv.y, 0.f);
            acc.z = fmaxf(acc.z * inv + bv.z, 0.f);
            acc.w = fmaxf(acc.w * inv + bv.w, 0.f);
        } else {
            acc.x *= inv; acc.y *= inv; acc.z *= inv; acc.w *= inv;
        }
        ((float4*)AGG)[(size_t)w * 32 + lane] = acc;
    } else {
        const unsigned* H1 = (const unsigned*)HB;
        float2 acc = make_float2(0.f, 0.f);
#pragma unroll 2
        for (int j = 0; j < n; j++) {
            int   s  = g_csrs[start + j];
            float ex = __expf(leaky(g_as[s] + adv) - m);
            ss += ex;
            unsigned v = H1[(size_t)s * 32 + lane];
            float2 f = __bfloat1622float2(*(__nv_bfloat162*)&v);
            acc.x += ex * f.x; acc.y += ex * f.y;
        }
        float inv = 1.f / (ss + 1e-16f);
        ((float2*)AGG)[(size_t)w * 32 + lane] = make_float2(acc.x * inv, acc.y * inv);
    }
}

// ---------------- output: out[c] = mean_n agg2[n][c] + b2[c] ----------------
__global__ void k_out_init(float* out, const float* __restrict__ b2) {
    if (threadIdx.x < DOUT) out[threadIdx.x] = b2[threadIdx.x];
}

__global__ void k_mean(const float* __restrict__ A, float* out, int N, float invN) {
    int col    = threadIdx.x & 63;
    int rgrp   = blockIdx.x * (blockDim.x >> 6) + (threadIdx.x >> 6);
    int stride = gridDim.x * (blockDim.x >> 6);
    float sum = 0.f;
    for (int n = rgrp; n < N; n += stride) sum += A[(size_t)n * DOUT + col];
    atomicAdd(&out[col], sum * invN);
}

// ---------------- host ----------------
extern "C" void kernel_launch(void* const* d_in, const int* in_sizes, int n_in,
                              void* d_out, int out_size) {
    const float* x   = (const float*)d_in[0];
    const int*   ei  = (const int*)d_in[1];     // int32 (JAX x64 disabled)
    const float* W1  = (const float*)d_in[2];
    const float* a1s = (const float*)d_in[3];
    const float* a1d = (const float*)d_in[4];
    const float* b1  = (const float*)d_in[5];
    const float* W2  = (const float*)d_in[6];
    const float* a2s = (const float*)d_in[7];
    const float* a2d = (const float*)d_in[8];
    const float* b2  = (const float*)d_in[9];
    float* out = (float*)d_out;

    int N = in_sizes[0] / DHID;   // 100000
    int E = in_sizes[1] / 2;      // 3200000
    const int* srcp = ei;
    const int* dstp = ei + E;

    __nv_bfloat16 *hb1, *hb2;
    float *agg1, *agg2;
    int *degp, *ctrp;
    cudaGetSymbolAddress((void**)&hb1,  g_hb1);
    cudaGetSymbolAddress((void**)&agg1, g_agg1);
    cudaGetSymbolAddress((void**)&hb2,  g_hb2);
    cudaGetSymbolAddress((void**)&agg2, g_agg2);
    cudaGetSymbolAddress((void**)&degp, g_deg);
    cudaGetSymbolAddress((void**)&ctrp, g_counter);

    const int smem1 = (128 * 128 + 64 * 128) * 4;  // 96KB
    const int smem2 = (128 * 64  + 64 * 128) * 4;  // 64KB
    cudaFuncSetAttribute(k_gemm2<128>, cudaFuncAttributeMaxDynamicSharedMemorySize, smem1);
    cudaFuncSetAttribute(k_gemm2<64>,  cudaFuncAttributeMaxDynamicSharedMemorySize, smem2);

    // lazily-created side stream + events (created outside capture on the
    // correctness call; only the launches below are captured)
    static cudaStream_t s2 = nullptr;
    static cudaEvent_t  evF = nullptr, evJ = nullptr;
    if (!s2) {
        cudaStreamCreateWithFlags(&s2, cudaStreamNonBlocking);
        cudaEventCreateWithFlags(&evF, cudaEventDisableTiming);
        cudaEventCreateWithFlags(&evJ, cudaEventDisableTiming);
    }

    int gemmBlks = (N + 63) / 64;
    int nodeBlks = (N + 255) / 256;
    int edgeBlks = (E + 255) / 256;
    int warpBlks = (N + 7) / 8;

    // ---------- fork: CSR build on s2, GEMM1 on main ----------
    cudaEventRecord(evF, 0);
    cudaStreamWaitEvent(s2, evF, 0);
    cudaMemsetAsync(degp, 0, (size_t)N * sizeof(int), s2);
    cudaMemsetAsync(ctrp, 0, sizeof(int), s2);
    k_hist   <<<edgeBlks, 256, 0, s2>>>(dstp, E);
    k_alloc  <<<nodeBlks, 256, 0, s2>>>(N);
    k_scatter<<<edgeBlks, 256, 0, s2>>>(srcp, dstp, E);
    cudaEventRecord(evJ, s2);

    k_gemm2<128><<<gemmBlks, 256, smem1>>>(x, W1, hb1, a1s, a1d, N);

    // ---------- join, then fused attention layer 1 ----------
    cudaStreamWaitEvent(0, evJ, 0);
    k_attn<128, true><<<warpBlks, 256>>>(hb1, agg1, b1, N);

    // ---------- layer 2 ----------
    k_gemm2<64><<<gemmBlks, 128, smem2>>>(agg1, W2, hb2, a2s, a2d, N);
    k_attn<64, false><<<warpBlks, 256>>>(hb2, agg2, (const float*)nullptr, N);

    // ---------- mean over nodes (+ b2) ----------
    k_out_init<<<1, 64>>>(out, b2);
    k_mean<<<256, 256>>>(agg2, out, N, 1.0f / (float)N);
}

// round 8
// speedup vs baseline: 1.1040x; 1.1040x over previous
#include <cuda_runtime.h>
#include <cuda_bf16.h>
#include <math.h>

// ---------------- problem constants ----------------
#define NMAX 100000
#define EMAX 3200000
#define DHID 128
#define DOUT 64

// ---------------- static scratch (allocation-free) ----------------
__device__ __nv_bfloat16 g_hb1[NMAX * DHID];   // layer1 GEMM out (bf16 for gather)
__device__ float g_agg1 [NMAX * DHID];         // layer1 aggregated (relu+bias fused)
__device__ __nv_bfloat16 g_hb2[NMAX * DOUT];   // layer2 GEMM out (bf16)
__device__ float g_agg2 [NMAX * DOUT];         // layer2 aggregated
__device__ float g_as   [NMAX];
__device__ float g_ad   [NMAX];
__device__ float g_inv  [NMAX];                // 1/(softmax denom)
__device__ float g_alpha[EMAX + NMAX];         // per-edge exp(e - m) in CSR order
__device__ int   g_deg  [NMAX];                // in-degree incl. self-loop
__device__ int   g_off  [NMAX];
__device__ int   g_cur  [NMAX];
__device__ int   g_csrs [EMAX + NMAX];
__device__ int   g_counter;

__device__ __forceinline__ float leaky(float e) { return e > 0.f ? e : 0.2f * e; }

// ---------------- CSR build ----------------
__global__ void k_hist(const int* __restrict__ dstp, int E) {
    int i = blockIdx.x * blockDim.x + threadIdx.x;
    if (i < E) atomicAdd(&g_deg[dstp[i]], 1);
}

__global__ void k_alloc(int N) {
    int i    = blockIdx.x * blockDim.x + threadIdx.x;
    int lane = threadIdx.x & 31;
    int v    = (i < N) ? (g_deg[i] + 1) : 0;   // +1 self-loop
    int incl = v;
#pragma unroll
    for (int o = 1; o < 32; o <<= 1) {
        int t = __shfl_up_sync(0xffffffffu, incl, o);
        if (lane >= o) incl += t;
    }
    int total = __shfl_sync(0xffffffffu, incl, 31);
    int base  = 0;
    if (lane == 0) base = atomicAdd(&g_counter, total);
    base = __shfl_sync(0xffffffffu, base, 0);
    if (i < N) {
        int my = base + incl - v;
        g_deg[i]   = v;
        g_off[i]   = my;
        g_csrs[my] = i;        // self-loop first
        g_cur[i]   = my + 1;
    }
}

__global__ void k_scatter(const int* __restrict__ srcp, const int* __restrict__ dstp, int E) {
    int i = blockIdx.x * blockDim.x + threadIdx.x;
    if (i < E) {
        int d   = dstp[i];
        int pos = atomicAdd(&g_cur[d], 1);
        g_csrs[pos] = srcp[i];
    }
}

// ---------------- GEMM (f32x2, K-chunked for occupancy) + fused dots + bf16 store ----------------
// Block: 64 rows x FOUT cols. Thread tile 4x8. K processed in two 64-chunks so
// smem = 48KB (FOUT=128) -> 4 CTAs/SM.
template<int FOUT>
__global__ void __launch_bounds__(FOUT * 2, 4)
k_gemm2(const float* __restrict__ X, const float* __restrict__ W,
        __nv_bfloat16* __restrict__ HB,
        const float* __restrict__ avs, const float* __restrict__ avd,
        int N) {
    constexpr int K   = 128;
    constexpr int KC  = 64;        // K-chunk
    constexpr int BR  = 64;
    constexpr int CG  = FOUT / 8;  // 16 or 8
    constexpr int NT  = CG * 16;   // 256 or 128 threads
    extern __shared__ float smem[];
    float* sW = smem;              // KC * FOUT
    float* sX = smem + KC * FOUT;  // BR * KC

    int tid  = threadIdx.x;
    int row0 = blockIdx.x * BR;
    int rows = N - row0; if (rows > BR) rows = BR;

    int tx = tid % CG;
    int ty = tid / CG;
    const unsigned long long* sW2 = (const unsigned long long*)sW;

    unsigned long long acc[4][4];
#pragma unroll
    for (int i = 0; i < 4; i++)
#pragma unroll
        for (int j = 0; j < 4; j++) acc[i][j] = 0ull;

#pragma unroll
    for (int kc = 0; kc < K / KC; kc++) {
        // stage W chunk [KC x FOUT] and X chunk [rows x KC]
        for (int i = tid; i < KC * FOUT / 4; i += NT)
            ((float4*)sW)[i] = ((const float4*)(W + kc * KC * FOUT))[i];
        {
            const float4* X4 = (const float4*)(X + (size_t)row0 * K + kc * KC);
            for (int i = tid; i < rows * (KC / 4); i += NT) {
                int r = i / (KC / 4), c = i % (KC / 4);
                ((float4*)sX)[r * (KC / 4) + c] = X4[r * (K / 4) + c];
            }
        }
        __syncthreads();

#pragma unroll 4
        for (int k = 0; k < KC; k++) {
            unsigned long long b0 = sW2[k * (FOUT / 2) + tx * 2];
            unsigned long long b1 = sW2[k * (FOUT / 2) + tx * 2 + 1];
            unsigned long long b2 = sW2[k * (FOUT / 2) + FOUT / 4 + tx * 2];
            unsigned long long b3 = sW2[k * (FOUT / 2) + FOUT / 4 + tx * 2 + 1];
#pragma unroll
            for (int i = 0; i < 4; i++) {
                unsigned xu = __float_as_uint(sX[(ty * 4 + i) * KC + k]);
                unsigned long long a2;
                asm("mov.b64 %0, {%1, %1};" : "=l"(a2) : "r"(xu));
                asm("fma.rn.f32x2 %0, %1, %2, %0;" : "+l"(acc[i][0]) : "l"(a2), "l"(b0));
                asm("fma.rn.f32x2 %0, %1, %2, %0;" : "+l"(acc[i][1]) : "l"(a2), "l"(b1));
                asm("fma.rn.f32x2 %0, %1, %2, %0;" : "+l"(acc[i][2]) : "l"(a2), "l"(b2));
                asm("fma.rn.f32x2 %0, %1, %2, %0;" : "+l"(acc[i][3]) : "l"(a2), "l"(b3));
            }
        }
        __syncthreads();
    }

    // ---- epilogue: unpack, bf16 store, fused attention dots ----
    int c0 = tx * 4, c1 = FOUT / 2 + tx * 4;
    float as0[4], as1[4], ad0[4], ad1[4];
#pragma unroll
    for (int j = 0; j < 4; j++) {
        as0[j] = __ldg(&avs[c0 + j]); as1[j] = __ldg(&avs[c1 + j]);
        ad0[j] = __ldg(&avd[c0 + j]); ad1[j] = __ldg(&avd[c1 + j]);
    }

#pragma unroll
    for (int i = 0; i < 4; i++) {
        int row = row0 + ty * 4 + i;
        float c[8];
#pragma unroll
        for (int j = 0; j < 4; j++) {
            unsigned lo, hi;
            asm("mov.b64 {%0, %1}, %2;" : "=r"(lo), "=r"(hi) : "l"(acc[i][j]));
            c[j * 2]     = __uint_as_float(lo);
            c[j * 2 + 1] = __uint_as_float(hi);
        }
        float s1 = c[0]*as0[0] + c[1]*as0[1] + c[2]*as0[2] + c[3]*as0[3]
                 + c[4]*as1[0] + c[5]*as1[1] + c[6]*as1[2] + c[7]*as1[3];
        float s2 = c[0]*ad0[0] + c[1]*ad0[1] + c[2]*ad0[2] + c[3]*ad0[3]
                 + c[4]*ad1[0] + c[5]*ad1[1] + c[6]*ad1[2] + c[7]*ad1[3];
#pragma unroll
        for (int o = CG / 2; o > 0; o >>= 1) {
            s1 += __shfl_xor_sync(0xffffffffu, s1, o);
            s2 += __shfl_xor_sync(0xffffffffu, s2, o);
        }
        if (row < N) {
            __nv_bfloat162 p0 = __float22bfloat162_rn(make_float2(c[0], c[1]));
            __nv_bfloat162 p1 = __float22bfloat162_rn(make_float2(c[2], c[3]));
            __nv_bfloat162 p2 = __float22bfloat162_rn(make_float2(c[4], c[5]));
            __nv_bfloat162 p3 = __float22bfloat162_rn(make_float2(c[6], c[7]));
            uint2 u, v;
            u.x = *(unsigned*)&p0; u.y = *(unsigned*)&p1;
            v.x = *(unsigned*)&p2; v.y = *(unsigned*)&p3;
            *(uint2*)(HB + (size_t)row * FOUT + c0) = u;
            *(uint2*)(HB + (size_t)row * FOUT + c1) = v;
            if (tx == 0) { g_as[row] = s1; g_ad[row] = s2; }
        }
    }
}

// ---------------- phase 1: segment softmax per dst node (warp per node) ----------------
__global__ void k_phase1(int N) {
    int w    = (blockIdx.x * blockDim.x + threadIdx.x) >> 5;
    int lane = threadIdx.x & 31;
    if (w >= N) return;
    int   start = g_off[w];
    int   n     = g_deg[w];
    float adv   = g_ad[w];

    if (n <= 32) {
        float e = -INFINITY;
        if (lane < n) {
            int s = g_csrs[start + lane];
            e = leaky(g_as[s] + adv);
        }
        float m = e;
#pragma unroll
        for (int o = 16; o > 0; o >>= 1) m = fmaxf(m, __shfl_xor_sync(0xffffffffu, m, o));
        float ex = (lane < n) ? __expf(e - m) : 0.f;
        float ss = ex;
#pragma unroll
        for (int o = 16; o > 0; o >>= 1) ss += __shfl_xor_sync(0xffffffffu, ss, o);
        if (lane < n) g_alpha[start + lane] = ex;
        if (lane == 0) g_inv[w] = 1.f / (ss + 1e-16f);
    } else {
        float m = -INFINITY;
        for (int j0 = 0; j0 < n; j0 += 32) {
            int j = j0 + lane;
            float e = -INFINITY;
            if (j < n) {
                int s = g_csrs[start + j];
                e = leaky(g_as[s] + adv);
                g_alpha[start + j] = e;
            }
            m = fmaxf(m, e);
        }
#pragma unroll
        for (int o = 16; o > 0; o >>= 1) m = fmaxf(m, __shfl_xor_sync(0xffffffffu, m, o));
        float ss = 0.f;
        for (int j0 = 0; j0 < n; j0 += 32) {
            int j = j0 + lane;
            if (j < n) {
                float ex = __expf(g_alpha[start + j] - m);
                g_alpha[start + j] = ex;
                ss += ex;
            }
        }
#pragma unroll
        for (int o = 16; o > 0; o >>= 1) ss += __shfl_xor_sync(0xffffffffu, ss, o);
        if (lane == 0) g_inv[w] = 1.f / (ss + 1e-16f);
    }
}

// ---------------- phase 2: bf16 gather-aggregate (warp per node) ----------------
__global__ void k_phase2_128(const __nv_bfloat16* __restrict__ HB, float* __restrict__ AGG,
                             const float* __restrict__ bias, int N) {
    int w    = (blockIdx.x * blockDim.x + threadIdx.x) >> 5;
    int lane = threadIdx.x & 31;
    if (w >= N) return;
    int start = g_off[w];
    int n     = g_deg[w];
    const uint2* H2 = (const uint2*)HB;

    float4 acc = make_float4(0.f, 0.f, 0.f, 0.f);
#pragma unroll 4
    for (int j = 0; j < n; j++) {
        int   s = g_csrs[start + j];
        float a = g_alpha[start + j];
        uint2 v = H2[(size_t)s * 32 + lane];
        float2 f0 = __bfloat1622float2(*(__nv_bfloat162*)&v.x);
        float2 f1 = __bfloat1622float2(*(__nv_bfloat162*)&v.y);
        acc.x += a * f0.x; acc.y += a * f0.y;
        acc.z += a * f1.x; acc.w += a * f1.y;
    }
    float inv = g_inv[w];
    float4 bv = ((const float4*)bias)[lane];
    acc.x = fmaxf(acc.x * inv + bv.x, 0.f);
    acc.y = fmaxf(acc.y * inv + bv.y, 0.f);
    acc.z = fmaxf(acc.z * inv + bv.z, 0.f);
    acc.w = fmaxf(acc.w * inv + bv.w, 0.f);
    ((float4*)AGG)[(size_t)w * 32 + lane] = acc;
}

__global__ void k_phase2_64(const __nv_bfloat16* __restrict__ HB, float* __restrict__ AGG,
                            int N) {
    int w    = (blockIdx.x * blockDim.x + threadIdx.x) >> 5;
    int lane = threadIdx.x & 31;
    if (w >= N) return;
    int start = g_off[w];
    int n     = g_deg[w];
    const unsigned* H1 = (const unsigned*)HB;

    float2 acc = make_float2(0.f, 0.f);
#pragma unroll 4
    for (int j = 0; j < n; j++) {
        int   s = g_csrs[start + j];
        float a = g_alpha[start + j];
        unsigned v = H1[(size_t)s * 32 + lane];
        float2 f = __bfloat1622float2(*(__nv_bfloat162*)&v);
        acc.x += a * f.x; acc.y += a * f.y;
    }
    float inv = g_inv[w];
    ((float2*)AGG)[(size_t)w * 32 + lane] = make_float2(acc.x * inv, acc.y * inv);
}

// ---------------- output: out[c] = mean_n agg2[n][c] + b2[c] ----------------
__global__ void k_out_init(float* out, const float* __restrict__ b2) {
    if (threadIdx.x < DOUT) out[threadIdx.x] = b2[threadIdx.x];
}

__global__ void k_mean(const float* __restrict__ A, float* out, int N, float invN) {
    int col    = threadIdx.x & 63;
    int rgrp   = blockIdx.x * (blockDim.x >> 6) + (threadIdx.x >> 6);
    int stride = gridDim.x * (blockDim.x >> 6);
    float sum = 0.f;
    for (int n = rgrp; n < N; n += stride) sum += A[(size_t)n * DOUT + col];
    atomicAdd(&out[col], sum * invN);
}

// ---------------- host ----------------
extern "C" void kernel_launch(void* const* d_in, const int* in_sizes, int n_in,
                              void* d_out, int out_size) {
    const float* x   = (const float*)d_in[0];
    const int*   ei  = (const int*)d_in[1];     // int32 (JAX x64 disabled)
    const float* W1  = (const float*)d_in[2];
    const float* a1s = (const float*)d_in[3];
    const float* a1d = (const float*)d_in[4];
    const float* b1  = (const float*)d_in[5];
    const float* W2  = (const float*)d_in[6];
    const float* a2s = (const float*)d_in[7];
    const float* a2d = (const float*)d_in[8];
    const float* b2  = (const float*)d_in[9];
    float* out = (float*)d_out;

    int N = in_sizes[0] / DHID;   // 100000
    int E = in_sizes[1] / 2;      // 3200000
    const int* srcp = ei;
    const int* dstp = ei + E;

    __nv_bfloat16 *hb1, *hb2;
    float *agg1, *agg2;
    int *degp, *ctrp;
    cudaGetSymbolAddress((void**)&hb1,  g_hb1);
    cudaGetSymbolAddress((void**)&agg1, g_agg1);
    cudaGetSymbolAddress((void**)&hb2,  g_hb2);
    cudaGetSymbolAddress((void**)&agg2, g_agg2);
    cudaGetSymbolAddress((void**)&degp, g_deg);
    cudaGetSymbolAddress((void**)&ctrp, g_counter);

    const int smem1 = (64 * 128 + 64 * 64) * 4;  // 48KB
    const int smem2 = (64 * 64  + 64 * 64) * 4;  // 32KB
    cudaFuncSetAttribute(k_gemm2<128>, cudaFuncAttributeMaxDynamicSharedMemorySize, smem1);
    cudaFuncSetAttribute(k_gemm2<64>,  cudaFuncAttributeMaxDynamicSharedMemorySize, smem2);

    static cudaStream_t s2 = nullptr;
    static cudaEvent_t  evF = nullptr, evJ = nullptr;
    if (!s2) {
        cudaStreamCreateWithFlags(&s2, cudaStreamNonBlocking);
        cudaEventCreateWithFlags(&evF, cudaEventDisableTiming);
        cudaEventCreateWithFlags(&evJ, cudaEventDisableTiming);
    }

    int gemmBlks = (N + 63) / 64;
    int nodeBlks = (N + 255) / 256;
    int edgeBlks = (E + 255) / 256;
    int warpBlks = (N + 7) / 8;

    // ---------- fork: CSR build on s2, GEMM1 on main ----------
    cudaEventRecord(evF, 0);
    cudaStreamWaitEvent(s2, evF, 0);
    cudaMemsetAsync(degp, 0, (size_t)N * sizeof(int), s2);
    cudaMemsetAsync(ctrp, 0, sizeof(int), s2);
    k_hist   <<<edgeBlks, 256, 0, s2>>>(dstp, E);
    k_alloc  <<<nodeBlks, 256, 0, s2>>>(N);
    k_scatter<<<edgeBlks, 256, 0, s2>>>(srcp, dstp, E);
    cudaEventRecord(evJ, s2);

    k_gemm2<128><<<gemmBlks, 256, smem1>>>(x, W1, hb1, a1s, a1d, N);

    // ---------- join, then layer-1 attention ----------
    cudaStreamWaitEvent(0, evJ, 0);
    k_phase1<<<warpBlks, 256>>>(N);
    k_phase2_128<<<warpBlks, 256>>>(hb1, agg1, b1, N);

    // ---------- layer 2 ----------
    k_gemm2<64><<<gemmBlks, 128, smem2>>>(agg1, W2, hb2, a2s, a2d, N);
    k_phase1<<<warpBlks, 256>>>(N);
    k_phase2_64<<<warpBlks, 256>>>(hb2, agg2, N);

    // ---------- mean over nodes (+ b2) ----------
    k_out_init<<<1, 64>>>(out, b2);
    k_mean<<<256, 256>>>(agg2, out, N, 1.0f / (float)N);
}